// round 12
// baseline (speedup 1.0000x reference)
#include <cuda_runtime.h>
#include <cuda_fp16.h>
#include <cstdint>

#define NN     8192
#define NFEAT  512
#define NHID   256
#define NCLASS 16
#define CAP    256

#define OUT0_OFF    0
#define ATT_OFF     (NN*NCLASS)
#define CONCAT_OFF  (ATT_OFF + (size_t)NN*NN)
#define CONCAT_W    (NHID + NCLASS)

// ---------------- scratch (16B-aligned: uint4/float4 access) ----------------
__device__ __align__(16) __half g_xW1h[NN*NHID];   // fp16 gather table (K2)
__device__ __align__(16) __half g_h1h [NN*NHID];   // fp16 h1 (K3 A, K4 input)
__device__ __align__(16) __half g_Whh [NN*NHID];   // fp16 gather table (K5)
__device__ __align__(16) float  g_aout[NN*NHID];
__device__ __align__(16) float  g_f1  [NN];
__device__ __align__(16) float  g_f2  [NN];
__device__ __align__(16) float  g_v1  [NHID];
__device__ __align__(16) float  g_v2  [NHID];
__device__ __align__(16) float  g_t16 [NN*NCLASS];
__device__ __align__(16) int    g_nbr [NN*CAP];
__device__ __align__(16) int    g_cnt [NN];

// ---------------- helpers ---------------------------------------------------
__device__ __forceinline__ float warpMax(float v) {
    #pragma unroll
    for (int o = 16; o > 0; o >>= 1) v = fmaxf(v, __shfl_xor_sync(0xffffffffu, v, o));
    return v;
}
__device__ __forceinline__ float warpSum(float v) {
    #pragma unroll
    for (int o = 16; o > 0; o >>= 1) v += __shfl_xor_sync(0xffffffffu, v, o);
    return v;
}
__device__ __forceinline__ uint32_t smem_u32(const void* p) {
    return (uint32_t)__cvta_generic_to_shared(p);
}
__device__ __forceinline__ void ldsm_x4(uint32_t& r0, uint32_t& r1, uint32_t& r2, uint32_t& r3, uint32_t a) {
    asm volatile("ldmatrix.sync.aligned.m8n8.x4.shared.b16 {%0,%1,%2,%3}, [%4];"
                 : "=r"(r0), "=r"(r1), "=r"(r2), "=r"(r3) : "r"(a));
}
__device__ __forceinline__ void ldsm_x4_t(uint32_t& r0, uint32_t& r1, uint32_t& r2, uint32_t& r3, uint32_t a) {
    asm volatile("ldmatrix.sync.aligned.m8n8.x4.trans.shared.b16 {%0,%1,%2,%3}, [%4];"
                 : "=r"(r0), "=r"(r1), "=r"(r2), "=r"(r3) : "r"(a));
}
__device__ __forceinline__ void mma16816(float* c, const uint32_t* a, const uint32_t* b) {
    asm volatile(
        "mma.sync.aligned.m16n8k16.row.col.f32.f16.f16.f32 "
        "{%0,%1,%2,%3},{%4,%5,%6,%7},{%8,%9},{%0,%1,%2,%3};"
        : "+f"(c[0]), "+f"(c[1]), "+f"(c[2]), "+f"(c[3])
        : "r"(a[0]), "r"(a[1]), "r"(a[2]), "r"(a[3]), "r"(b[0]), "r"(b[1]));
}
__device__ __forceinline__ uint2 split_pack(float4 v, uint2& lo) {
    __half hx = __float2half_rn(v.x), hy = __float2half_rn(v.y);
    __half hz = __float2half_rn(v.z), hw = __float2half_rn(v.w);
    __half2 hi01 = __halves2half2(hx, hy), hi23 = __halves2half2(hz, hw);
    __half2 lo01 = __floats2half2_rn(v.x - __half2float(hx), v.y - __half2float(hy));
    __half2 lo23 = __floats2half2_rn(v.z - __half2float(hz), v.w - __half2float(hw));
    uint2 hi;
    hi.x = *reinterpret_cast<uint32_t*>(&hi01); hi.y = *reinterpret_cast<uint32_t*>(&hi23);
    lo.x = *reinterpret_cast<uint32_t*>(&lo01); lo.y = *reinterpret_cast<uint32_t*>(&lo23);
    return hi;
}
// accumulate 8 cols from one uint4 of halves
__device__ __forceinline__ void acc8(const uint4 v, float s, float* a) {
    const __half2* h = reinterpret_cast<const __half2*>(&v);
    #pragma unroll
    for (int j = 0; j < 4; j++) {
        float2 f = __half22float2(h[j]);
        a[2*j]   = fmaf(s, f.x, a[2*j]);
        a[2*j+1] = fmaf(s, f.y, a[2*j+1]);
    }
}
__device__ __forceinline__ void add8(const uint4 v, float* a) {
    const __half2* h = reinterpret_cast<const __half2*>(&v);
    #pragma unroll
    for (int j = 0; j < 4; j++) {
        float2 f = __half22float2(h[j]);
        a[2*j]   += f.x;
        a[2*j+1] += f.y;
    }
}

// ---------------- K1: split-fp16 HMMA GEMM (3-pass) -> fp16 table -----------
#define HBM 128
#define HBN 64
#define HBK 32
__global__ __launch_bounds__(256) void hgemm_split(
    const float* __restrict__ A, const float* __restrict__ B,
    __half* __restrict__ Ch, int M, int K, int N)
{
    __shared__ __align__(16) __half Ahi[HBM][HBK + 8];
    __shared__ __align__(16) __half Alo[HBM][HBK + 8];
    __shared__ __align__(16) __half Bhi[HBK][HBN + 8];
    __shared__ __align__(16) __half Blo[HBK][HBN + 8];

    const int t    = threadIdx.x;
    const int wid  = t >> 5, lane = t & 31;
    const int wm   = (wid & 3) * 32;
    const int wn   = (wid >> 2) * 32;
    const int bm   = blockIdx.y * HBM;
    const int bn   = blockIdx.x * HBN;

    float acc[2][4][4];
    #pragma unroll
    for (int i = 0; i < 2; i++)
        #pragma unroll
        for (int j = 0; j < 4; j++)
            #pragma unroll
            for (int q = 0; q < 4; q++) acc[i][j][q] = 0.f;

    const int la = lane & 15, lb = lane >> 4;

    for (int k0 = 0; k0 < K; k0 += HBK) {
        #pragma unroll
        for (int q = 0; q < 4; q++) {
            int i = t + 256 * q;
            int r = i >> 3, cc = (i & 7) * 4;
            float4 v = *reinterpret_cast<const float4*>(&A[(size_t)(bm + r) * K + k0 + cc]);
            uint2 lo, hi = split_pack(v, lo);
            *reinterpret_cast<uint2*>(&Ahi[r][cc]) = hi;
            *reinterpret_cast<uint2*>(&Alo[r][cc]) = lo;
        }
        #pragma unroll
        for (int q = 0; q < 2; q++) {
            int i = t + 256 * q;
            int r = i >> 4, cc = (i & 15) * 4;
            float4 v = *reinterpret_cast<const float4*>(&B[(size_t)(k0 + r) * N + bn + cc]);
            uint2 lo, hi = split_pack(v, lo);
            *reinterpret_cast<uint2*>(&Bhi[r][cc]) = hi;
            *reinterpret_cast<uint2*>(&Blo[r][cc]) = lo;
        }
        __syncthreads();

        #pragma unroll
        for (int kk = 0; kk < 2; kk++) {
            uint32_t ah[2][4], al[2][4], bh[4][2], bl[4][2];
            #pragma unroll
            for (int mf = 0; mf < 2; mf++) {
                ldsm_x4(ah[mf][0], ah[mf][1], ah[mf][2], ah[mf][3],
                        smem_u32(&Ahi[wm + mf * 16 + la][kk * 16 + lb * 8]));
                ldsm_x4(al[mf][0], al[mf][1], al[mf][2], al[mf][3],
                        smem_u32(&Alo[wm + mf * 16 + la][kk * 16 + lb * 8]));
            }
            #pragma unroll
            for (int g = 0; g < 2; g++) {
                ldsm_x4_t(bh[g*2][0], bh[g*2][1], bh[g*2+1][0], bh[g*2+1][1],
                          smem_u32(&Bhi[kk * 16 + la][wn + g * 16 + lb * 8]));
                ldsm_x4_t(bl[g*2][0], bl[g*2][1], bl[g*2+1][0], bl[g*2+1][1],
                          smem_u32(&Blo[kk * 16 + la][wn + g * 16 + lb * 8]));
            }
            #pragma unroll
            for (int mf = 0; mf < 2; mf++)
                #pragma unroll
                for (int nf = 0; nf < 4; nf++) {
                    mma16816(acc[mf][nf], ah[mf], bh[nf]);
                    mma16816(acc[mf][nf], ah[mf], bl[nf]);
                    mma16816(acc[mf][nf], al[mf], bh[nf]);
                }
        }
        __syncthreads();
    }

    #pragma unroll
    for (int mf = 0; mf < 2; mf++)
        #pragma unroll
        for (int nf = 0; nf < 4; nf++) {
            int gm = bm + wm + mf * 16 + (lane >> 2);
            int gn = bn + wn + nf * 8 + (lane & 3) * 2;
            float* c = acc[mf][nf];
            *reinterpret_cast<__half2*>(&Ch[(size_t)gm * N + gn])       = __floats2half2_rn(c[0], c[1]);
            *reinterpret_cast<__half2*>(&Ch[(size_t)(gm + 8) * N + gn]) = __floats2half2_rn(c[2], c[3]);
        }
}

// ---------------- K3: HMMA GEMM, A fp16 direct, B fp32 split -> fp16 --------
__global__ __launch_bounds__(256) void hgemm_a16(
    const __half* __restrict__ A, const float* __restrict__ B,
    __half* __restrict__ Ch, int M, int K, int N)
{
    __shared__ __align__(16) __half Ahi[HBM][HBK + 8];
    __shared__ __align__(16) __half Bhi[HBK][HBN + 8];
    __shared__ __align__(16) __half Blo[HBK][HBN + 8];

    const int t    = threadIdx.x;
    const int wid  = t >> 5, lane = t & 31;
    const int wm   = (wid & 3) * 32;
    const int wn   = (wid >> 2) * 32;
    const int bm   = blockIdx.y * HBM;
    const int bn   = blockIdx.x * HBN;

    float acc[2][4][4];
    #pragma unroll
    for (int i = 0; i < 2; i++)
        #pragma unroll
        for (int j = 0; j < 4; j++)
            #pragma unroll
            for (int q = 0; q < 4; q++) acc[i][j][q] = 0.f;

    const int la = lane & 15, lb = lane >> 4;

    for (int k0 = 0; k0 < K; k0 += HBK) {
        #pragma unroll
        for (int q = 0; q < 2; q++) {
            int i = t + 256 * q;
            int r = i >> 2, c8 = (i & 3) * 8;
            uint4 v = *reinterpret_cast<const uint4*>(&A[(size_t)(bm + r) * K + k0 + c8]);
            *reinterpret_cast<uint4*>(&Ahi[r][c8]) = v;
        }
        #pragma unroll
        for (int q = 0; q < 2; q++) {
            int i = t + 256 * q;
            int r = i >> 4, cc = (i & 15) * 4;
            float4 v = *reinterpret_cast<const float4*>(&B[(size_t)(k0 + r) * N + bn + cc]);
            uint2 lo, hi = split_pack(v, lo);
            *reinterpret_cast<uint2*>(&Bhi[r][cc]) = hi;
            *reinterpret_cast<uint2*>(&Blo[r][cc]) = lo;
        }
        __syncthreads();

        #pragma unroll
        for (int kk = 0; kk < 2; kk++) {
            uint32_t ah[2][4], bh[4][2], bl[4][2];
            #pragma unroll
            for (int mf = 0; mf < 2; mf++)
                ldsm_x4(ah[mf][0], ah[mf][1], ah[mf][2], ah[mf][3],
                        smem_u32(&Ahi[wm + mf * 16 + la][kk * 16 + lb * 8]));
            #pragma unroll
            for (int g = 0; g < 2; g++) {
                ldsm_x4_t(bh[g*2][0], bh[g*2][1], bh[g*2+1][0], bh[g*2+1][1],
                          smem_u32(&Bhi[kk * 16 + la][wn + g * 16 + lb * 8]));
                ldsm_x4_t(bl[g*2][0], bl[g*2][1], bl[g*2+1][0], bl[g*2+1][1],
                          smem_u32(&Blo[kk * 16 + la][wn + g * 16 + lb * 8]));
            }
            #pragma unroll
            for (int mf = 0; mf < 2; mf++)
                #pragma unroll
                for (int nf = 0; nf < 4; nf++) {
                    mma16816(acc[mf][nf], ah[mf], bh[nf]);
                    mma16816(acc[mf][nf], ah[mf], bl[nf]);
                }
        }
        __syncthreads();
    }

    #pragma unroll
    for (int mf = 0; mf < 2; mf++)
        #pragma unroll
        for (int nf = 0; nf < 4; nf++) {
            int gm = bm + wm + mf * 16 + (lane >> 2);
            int gn = bn + wn + nf * 8 + (lane & 3) * 2;
            float* c = acc[mf][nf];
            *reinterpret_cast<__half2*>(&Ch[(size_t)gm * N + gn])       = __floats2half2_rn(c[0], c[1]);
            *reinterpret_cast<__half2*>(&Ch[(size_t)(gm + 8) * N + gn]) = __floats2half2_rn(c[2], c[3]);
        }
}

// ---------------- KV: v1 = Wa @ a1, v2 = Wa @ a2 ----------------------------
__global__ __launch_bounds__(256) void kv_v12(const float* __restrict__ Wa,
                                              const float* __restrict__ a_vec)
{
    __shared__ float a1[NHID], a2[NHID];
    const int t = threadIdx.x;
    a1[t] = a_vec[t];
    a2[t] = a_vec[NHID + t];
    __syncthreads();
    const float* wr = Wa + (size_t)t * NHID;
    float s1 = 0.f, s2 = 0.f;
    #pragma unroll 8
    for (int j = 0; j < NHID; j++) {
        float w = wr[j];
        s1 = fmaf(w, a1[j], s1);
        s2 = fmaf(w, a2[j], s2);
    }
    g_v1[t] = s1;
    g_v2[t] = s2;
}

// ---------------- K02: fused adjacency scan + spmm + relu -------------------
__global__ __launch_bounds__(256) void k02_fused(const int* __restrict__ adj,
                                                 const float* __restrict__ b1,
                                                 float* __restrict__ d_out)
{
    const int row = blockIdx.x;
    const int t   = threadIdx.x;
    const int lane = t & 31, wid = t >> 5;
    __shared__ __align__(16) float part[8][NHID];   // float4 access — 16B!
    __shared__ __align__(16) int nboff[CAP];
    __shared__ int warpTot[8], warpOff[8];
    __shared__ int sh_cnt;

    // ---- scan ----
    const int4* arow = reinterpret_cast<const int4*>(adj + (size_t)row * NN);
    int4 vv[8];
    int c = 0;
    #pragma unroll
    for (int q = 0; q < 8; q++) {
        vv[q] = arow[t * 8 + q];
        c += (vv[q].x != 0) + (vv[q].y != 0) + (vv[q].z != 0) + (vv[q].w != 0);
    }
    int sc = c;
    #pragma unroll
    for (int d = 1; d < 32; d <<= 1) {
        int o = __shfl_up_sync(0xffffffffu, sc, d);
        if (lane >= d) sc += o;
    }
    if (lane == 31) warpTot[wid] = sc;
    __syncthreads();
    if (t == 0) {
        int s = 0;
        #pragma unroll
        for (int w = 0; w < 8; w++) { warpOff[w] = s; s += warpTot[w]; }
        sh_cnt = min(s, CAP);
        g_cnt[row] = sh_cnt;
    }
    __syncthreads();

    int w = warpOff[wid] + sc - c;
    int* dst = g_nbr + (size_t)row * CAP;
    #pragma unroll
    for (int q = 0; q < 8; q++) {
        int base = t * 32 + q * 4;
        if (vv[q].x && w < CAP) { dst[w] = base + 0; nboff[w] = (base + 0) << 9; w++; }
        if (vv[q].y && w < CAP) { dst[w] = base + 1; nboff[w] = (base + 1) << 9; w++; }
        if (vv[q].z && w < CAP) { dst[w] = base + 2; nboff[w] = (base + 2) << 9; w++; }
        if (vv[q].w && w < CAP) { dst[w] = base + 3; nboff[w] = (base + 3) << 9; w++; }
    }
    __syncthreads();
    const int cnt = sh_cnt;

    // ---- gather: warp p handles neighbors p, p+8, ...; lane = 8-col group --
    const char* base = (const char*)g_xW1h;
    const int c16 = lane * 16;
    float a[8] = {0.f, 0.f, 0.f, 0.f, 0.f, 0.f, 0.f, 0.f};
    int i = wid;
    for (; i + 8 < cnt; i += 16) {
        uint4 v0 = *reinterpret_cast<const uint4*>(base + nboff[i]     + c16);
        uint4 v1 = *reinterpret_cast<const uint4*>(base + nboff[i + 8] + c16);
        add8(v0, a); add8(v1, a);
    }
    for (; i < cnt; i += 8) {
        uint4 v = *reinterpret_cast<const uint4*>(base + nboff[i] + c16);
        add8(v, a);
    }
    *reinterpret_cast<float4*>(&part[wid][lane * 8])     = make_float4(a[0], a[1], a[2], a[3]);
    *reinterpret_cast<float4*>(&part[wid][lane * 8 + 4]) = make_float4(a[4], a[5], a[6], a[7]);
    __syncthreads();

    if (t < 128) {
        const int c2 = t;
        float sx = 0.f, sy = 0.f;
        #pragma unroll
        for (int p = 0; p < 8; p++) { sx += part[p][2*c2]; sy += part[p][2*c2+1]; }
        float2 b = reinterpret_cast<const float2*>(b1)[c2];
        float vx = fmaxf(sx + b.x, 0.f);
        float vy = fmaxf(sy + b.y, 0.f);
        reinterpret_cast<__half2*>(g_h1h + (size_t)row * NHID)[c2] = __floats2half2_rn(vx, vy);
        reinterpret_cast<float2*>(d_out + CONCAT_OFF + (size_t)row * CONCAT_W)[c2] = make_float2(vx, vy);
    }
}

// ---------------- K4: f1 = h1 @ v1, f2 = h1 @ v2 (h1 fp16) ------------------
__global__ void k4_f12() {
    const int row = blockIdx.x * 8 + threadIdx.y;
    const int lane = threadIdx.x;
    float s1 = 0.f, s2 = 0.f;
    const __half2* h = reinterpret_cast<const __half2*>(g_h1h + (size_t)row * NHID);
    #pragma unroll
    for (int c2 = lane; c2 < 128; c2 += 32) {
        float2 f = __half22float2(h[c2]);
        s1 = fmaf(f.x, g_v1[2*c2], fmaf(f.y, g_v1[2*c2+1], s1));
        s2 = fmaf(f.x, g_v2[2*c2], fmaf(f.y, g_v2[2*c2+1], s2));
    }
    s1 = warpSum(s1); s2 = warpSum(s2);
    if (lane == 0) { g_f1[row] = s1; g_f2[row] = s2; }
}

// ---------------- K5: masked softmax + sparse scatter + h' + elu ------------
__global__ __launch_bounds__(256) void k5_attention(float* __restrict__ d_out)
{
    const int row = blockIdx.x;
    const int t   = threadIdx.x;
    const int lane = t & 31, wid = t >> 5;
    __shared__ __align__(16) float part[8][NHID];   // float4 access — 16B!
    __shared__ __align__(16) int   nboff[CAP];
    __shared__ int   nb[CAP];
    __shared__ float av[CAP];
    __shared__ float red[8];

    const int cnt = min(g_cnt[row], CAP);
    for (int i = t; i < cnt; i += 256) {
        int n = g_nbr[(size_t)row * CAP + i];
        nb[i] = n;
        nboff[i] = n << 9;
    }
    __syncthreads();

    const float fi = g_f1[row];
    float e = -1e30f;
    if (t < cnt) {
        float z = fi + g_f2[nb[t]];
        e = z > 0.f ? z : 0.01f * z;
    }
    float wm = warpMax(e);
    if (lane == 0) red[wid] = wm;
    __syncthreads();
    if (wid == 0) {
        float v = (lane < 8) ? red[lane] : -1e30f;
        v = warpMax(v);
        if (lane == 0) red[0] = v;
    }
    __syncthreads();
    const float m = red[0];
    __syncthreads();
    float p = (t < cnt) ? expf(e - m) : 0.f;
    float ws = warpSum(p);
    if (lane == 0) red[wid] = ws;
    __syncthreads();
    if (wid == 0) {
        float v = (lane < 8) ? red[lane] : 0.f;
        v = warpSum(v);
        if (lane == 0) red[0] = v;
    }
    __syncthreads();
    const float inv_s = 1.f / red[0];
    if (t < cnt) {
        float a = p * inv_s;
        av[t] = a;
        d_out[ATT_OFF + (size_t)row * NN + nb[t]] = a;
    }
    __syncthreads();

    // h_prime[row] = sum_j av[j] * Whh[nb[j]]  (fp16 table, uint4 loads)
    const char* base = (const char*)g_Whh;
    const int c16 = lane * 16;
    float a[8] = {0.f, 0.f, 0.f, 0.f, 0.f, 0.f, 0.f, 0.f};
    int i = wid;
    for (; i + 8 < cnt; i += 16) {
        float s0 = av[i], s1 = av[i + 8];
        uint4 v0 = *reinterpret_cast<const uint4*>(base + nboff[i]     + c16);
        uint4 v1 = *reinterpret_cast<const uint4*>(base + nboff[i + 8] + c16);
        acc8(v0, s0, a); acc8(v1, s1, a);
    }
    for (; i < cnt; i += 8) {
        uint4 v = *reinterpret_cast<const uint4*>(base + nboff[i] + c16);
        acc8(v, av[i], a);
    }
    *reinterpret_cast<float4*>(&part[wid][lane * 8])     = make_float4(a[0], a[1], a[2], a[3]);
    *reinterpret_cast<float4*>(&part[wid][lane * 8 + 4]) = make_float4(a[4], a[5], a[6], a[7]);
    __syncthreads();

    if (t < 128) {
        const int c2 = t;
        float sx = 0.f, sy = 0.f;
        #pragma unroll
        for (int p = 0; p < 8; p++) { sx += part[p][2*c2]; sy += part[p][2*c2+1]; }
        float ox = sx > 0.f ? sx : (expf(sx) - 1.f);
        float oy = sy > 0.f ? sy : (expf(sy) - 1.f);
        reinterpret_cast<float2*>(g_aout + (size_t)row * NHID)[c2] = make_float2(ox, oy);
    }
}

// ---------------- K6: t16 = a_out @ W3 --------------------------------------
__global__ __launch_bounds__(256) void k6_gemm3(const float* __restrict__ W3)
{
    __shared__ float As[16][257];
    __shared__ float Ws[NHID][16];
    const int t = threadIdx.x;
    const int row0 = blockIdx.x * 16;

    for (int idx = t; idx < 16 * NHID; idx += 256)
        As[idx >> 8][idx & 255] = g_aout[(size_t)(row0 + (idx >> 8)) * NHID + (idx & 255)];
    for (int idx = t; idx < NHID * 16; idx += 256)
        Ws[idx >> 4][idx & 15] = W3[idx];
    __syncthreads();

    const int r = t >> 4, c = t & 15;
    float acc = 0.f;
    #pragma unroll 8
    for (int k = 0; k < NHID; k++) acc = fmaf(As[r][k], Ws[k][c], acc);
    g_t16[(size_t)(row0 + r) * NCLASS + c] = acc;
}

// ---------------- K7: out = gather(t16) + b3 -> sigmoid + concat ------------
__global__ __launch_bounds__(256) void k7_final(const float* __restrict__ b3,
                                                float* __restrict__ d_out)
{
    const int t = threadIdx.x;
    const int row = blockIdx.x * 16 + (t >> 4);
    const int c = t & 15;
    const int cnt = g_cnt[row];
    const int* nbr = g_nbr + (size_t)row * CAP;

    float acc = 0.f;
    int i = 0;
    for (; i + 4 <= cnt; i += 4) {
        int n0 = nbr[i], n1 = nbr[i + 1], n2 = nbr[i + 2], n3 = nbr[i + 3];
        float v0 = g_t16[(size_t)n0 * NCLASS + c];
        float v1 = g_t16[(size_t)n1 * NCLASS + c];
        float v2 = g_t16[(size_t)n2 * NCLASS + c];
        float v3 = g_t16[(size_t)n3 * NCLASS + c];
        acc += (v0 + v1) + (v2 + v3);
    }
    for (; i < cnt; i++) acc += g_t16[(size_t)nbr[i] * NCLASS + c];

    float o = acc + b3[c];
    d_out[OUT0_OFF + (size_t)row * NCLASS + c] = 1.f / (1.f + expf(-o));
    d_out[CONCAT_OFF + (size_t)row * CONCAT_W + NHID + c] = o;
}

// ---------------- launch -----------------------------------------------------
extern "C" void kernel_launch(void* const* d_in, const int* in_sizes, int n_in,
                              void* d_out_v, int out_size)
{
    const float* x     = (const float*)d_in[0];
    const int*   adj   = (const int*)  d_in[1];
    const float* W1    = (const float*)d_in[2];
    const float* b1    = (const float*)d_in[3];
    const float* Wa    = (const float*)d_in[4];
    const float* a_vec = (const float*)d_in[5];
    const float* W3    = (const float*)d_in[6];
    const float* b3    = (const float*)d_in[7];
    float* d_out = (float*)d_out_v;

    __half *p_xW1h, *p_h1h, *p_Whh;
    cudaGetSymbolAddress((void**)&p_xW1h, g_xW1h);
    cudaGetSymbolAddress((void**)&p_h1h,  g_h1h);
    cudaGetSymbolAddress((void**)&p_Whh,  g_Whh);

    static cudaStream_t sSet = nullptr, sV = nullptr;
    static cudaEvent_t evRoot = nullptr, evSet = nullptr, evH1 = nullptr, evF = nullptr;
    if (!sSet) {
        cudaStreamCreateWithFlags(&sSet, cudaStreamNonBlocking);
        cudaStreamCreateWithFlags(&sV,   cudaStreamNonBlocking);
        cudaEventCreateWithFlags(&evRoot, cudaEventDisableTiming);
        cudaEventCreateWithFlags(&evSet,  cudaEventDisableTiming);
        cudaEventCreateWithFlags(&evH1,   cudaEventDisableTiming);
        cudaEventCreateWithFlags(&evF,    cudaEventDisableTiming);
    }
    cudaStream_t s0 = (cudaStream_t)0;

    cudaEventRecord(evRoot, s0);
    cudaStreamWaitEvent(sSet, evRoot, 0);
    cudaStreamWaitEvent(sV,   evRoot, 0);

    // side B: zero attention region
    cudaMemsetAsync(d_out + ATT_OFF, 0, (size_t)NN * NN * sizeof(float), sSet);
    cudaEventRecord(evSet, sSet);

    // side C: v1/v2
    kv_v12<<<1, 256, 0, sV>>>(Wa, a_vec);

    // main: K1 -> fp16 table
    hgemm_split<<<dim3(NHID / HBN, NN / HBM), 256, 0, s0>>>(x, W1, p_xW1h, NN, NFEAT, NHID);

    // main: fused scan + spmm + relu
    k02_fused<<<NN, 256, 0, s0>>>(adj, b1, d_out);
    cudaEventRecord(evH1, s0);

    // side C: f1/f2 (parallel with K3)
    cudaStreamWaitEvent(sV, evH1, 0);
    k4_f12<<<NN / 8, dim3(32, 8), 0, sV>>>();
    cudaEventRecord(evF, sV);

    // main: K3 -> fp16 Wh table
    hgemm_a16<<<dim3(NHID / HBN, NN / HBM), 256, 0, s0>>>(p_h1h, Wa, p_Whh, NN, NHID, NHID);

    // join -> K5
    cudaStreamWaitEvent(s0, evF, 0);
    cudaStreamWaitEvent(s0, evSet, 0);
    k5_attention<<<NN, 256, 0, s0>>>(d_out);

    k6_gemm3<<<NN / 16, 256, 0, s0>>>(W3);
    k7_final<<<NN / 16, 256, 0, s0>>>(b3, d_out);
}

// round 13
// speedup vs baseline: 1.0737x; 1.0737x over previous
#include <cuda_runtime.h>
#include <cuda_fp16.h>
#include <cstdint>

#define NN     8192
#define NFEAT  512
#define NHID   256
#define NCLASS 16
#define CAP    256

#define OUT0_OFF    0
#define ATT_OFF     (NN*NCLASS)
#define CONCAT_OFF  (ATT_OFF + (size_t)NN*NN)
#define CONCAT_W    (NHID + NCLASS)

// ---------------- scratch (16B-aligned) -------------------------------------
__device__ __align__(16) float  g_xW1 [NN*NHID];   // fp32 gather table (feat accuracy)
__device__ __align__(16) __half g_h1h [NN*NHID];   // fp16 h1 (K3 A, K4 input)
__device__ __align__(16) __half g_Whh [NN*NHID];   // fp16 gather table (K5)
__device__ __align__(16) float  g_aout[NN*NHID];
__device__ __align__(16) float  g_f1  [NN];
__device__ __align__(16) float  g_f2  [NN];
__device__ __align__(16) float  g_v1  [NHID];
__device__ __align__(16) float  g_v2  [NHID];
__device__ __align__(16) float  g_t16 [NN*NCLASS];
__device__ __align__(16) int    g_nbr [NN*CAP];
__device__ __align__(16) int    g_cnt [NN];

// ---------------- helpers ---------------------------------------------------
__device__ __forceinline__ float warpMax(float v) {
    #pragma unroll
    for (int o = 16; o > 0; o >>= 1) v = fmaxf(v, __shfl_xor_sync(0xffffffffu, v, o));
    return v;
}
__device__ __forceinline__ float warpSum(float v) {
    #pragma unroll
    for (int o = 16; o > 0; o >>= 1) v += __shfl_xor_sync(0xffffffffu, v, o);
    return v;
}
__device__ __forceinline__ uint32_t smem_u32(const void* p) {
    return (uint32_t)__cvta_generic_to_shared(p);
}
__device__ __forceinline__ void ldsm_x4(uint32_t& r0, uint32_t& r1, uint32_t& r2, uint32_t& r3, uint32_t a) {
    asm volatile("ldmatrix.sync.aligned.m8n8.x4.shared.b16 {%0,%1,%2,%3}, [%4];"
                 : "=r"(r0), "=r"(r1), "=r"(r2), "=r"(r3) : "r"(a));
}
__device__ __forceinline__ void ldsm_x4_t(uint32_t& r0, uint32_t& r1, uint32_t& r2, uint32_t& r3, uint32_t a) {
    asm volatile("ldmatrix.sync.aligned.m8n8.x4.trans.shared.b16 {%0,%1,%2,%3}, [%4];"
                 : "=r"(r0), "=r"(r1), "=r"(r2), "=r"(r3) : "r"(a));
}
__device__ __forceinline__ void mma16816(float* c, const uint32_t* a, const uint32_t* b) {
    asm volatile(
        "mma.sync.aligned.m16n8k16.row.col.f32.f16.f16.f32 "
        "{%0,%1,%2,%3},{%4,%5,%6,%7},{%8,%9},{%0,%1,%2,%3};"
        : "+f"(c[0]), "+f"(c[1]), "+f"(c[2]), "+f"(c[3])
        : "r"(a[0]), "r"(a[1]), "r"(a[2]), "r"(a[3]), "r"(b[0]), "r"(b[1]));
}
__device__ __forceinline__ uint2 split_pack(float4 v, uint2& lo) {
    __half hx = __float2half_rn(v.x), hy = __float2half_rn(v.y);
    __half hz = __float2half_rn(v.z), hw = __float2half_rn(v.w);
    __half2 hi01 = __halves2half2(hx, hy), hi23 = __halves2half2(hz, hw);
    __half2 lo01 = __floats2half2_rn(v.x - __half2float(hx), v.y - __half2float(hy));
    __half2 lo23 = __floats2half2_rn(v.z - __half2float(hz), v.w - __half2float(hw));
    uint2 hi;
    hi.x = *reinterpret_cast<uint32_t*>(&hi01); hi.y = *reinterpret_cast<uint32_t*>(&hi23);
    lo.x = *reinterpret_cast<uint32_t*>(&lo01); lo.y = *reinterpret_cast<uint32_t*>(&lo23);
    return hi;
}
// accumulate 8 cols from one uint4 of halves
__device__ __forceinline__ void acc8(const uint4 v, float s, float* a) {
    const __half2* h = reinterpret_cast<const __half2*>(&v);
    #pragma unroll
    for (int j = 0; j < 4; j++) {
        float2 f = __half22float2(h[j]);
        a[2*j]   = fmaf(s, f.x, a[2*j]);
        a[2*j+1] = fmaf(s, f.y, a[2*j+1]);
    }
}

// ---------------- K0: adjacency scan (ballot/shfl, 2 barriers) --------------
__global__ void k0_scan_adj(const int* __restrict__ adj) {
    const int row = blockIdx.x;
    const int t   = threadIdx.x;
    const int lane = t & 31, wid = t >> 5;
    __shared__ int warpTot[8], warpOff[8];

    const int4* arow = reinterpret_cast<const int4*>(adj + (size_t)row * NN);
    int4 vv[8];
    int c = 0;
    #pragma unroll
    for (int q = 0; q < 8; q++) {
        vv[q] = arow[t * 8 + q];
        c += (vv[q].x != 0) + (vv[q].y != 0) + (vv[q].z != 0) + (vv[q].w != 0);
    }
    int sc = c;
    #pragma unroll
    for (int d = 1; d < 32; d <<= 1) {
        int o = __shfl_up_sync(0xffffffffu, sc, d);
        if (lane >= d) sc += o;
    }
    if (lane == 31) warpTot[wid] = sc;
    __syncthreads();
    if (t == 0) {
        int s = 0;
        #pragma unroll
        for (int w = 0; w < 8; w++) { warpOff[w] = s; s += warpTot[w]; }
        g_cnt[row] = min(s, CAP);
    }
    __syncthreads();

    int w = warpOff[wid] + sc - c;
    int* dst = g_nbr + (size_t)row * CAP;
    #pragma unroll
    for (int q = 0; q < 8; q++) {
        int base = t * 32 + q * 4;
        if (vv[q].x && w < CAP) dst[w++] = base + 0;
        if (vv[q].y && w < CAP) dst[w++] = base + 1;
        if (vv[q].z && w < CAP) dst[w++] = base + 2;
        if (vv[q].w && w < CAP) dst[w++] = base + 3;
    }
}

// ---------------- K1: split-fp16 HMMA GEMM (3-pass) -> fp32 C ---------------
#define HBM 128
#define HBN 64
#define HBK 32
__global__ __launch_bounds__(256) void hgemm_split(
    const float* __restrict__ A, const float* __restrict__ B,
    float* __restrict__ C, int M, int K, int N)
{
    __shared__ __align__(16) __half Ahi[HBM][HBK + 8];
    __shared__ __align__(16) __half Alo[HBM][HBK + 8];
    __shared__ __align__(16) __half Bhi[HBK][HBN + 8];
    __shared__ __align__(16) __half Blo[HBK][HBN + 8];

    const int t    = threadIdx.x;
    const int wid  = t >> 5, lane = t & 31;
    const int wm   = (wid & 3) * 32;
    const int wn   = (wid >> 2) * 32;
    const int bm   = blockIdx.y * HBM;
    const int bn   = blockIdx.x * HBN;

    float acc[2][4][4];
    #pragma unroll
    for (int i = 0; i < 2; i++)
        #pragma unroll
        for (int j = 0; j < 4; j++)
            #pragma unroll
            for (int q = 0; q < 4; q++) acc[i][j][q] = 0.f;

    const int la = lane & 15, lb = lane >> 4;

    for (int k0 = 0; k0 < K; k0 += HBK) {
        #pragma unroll
        for (int q = 0; q < 4; q++) {
            int i = t + 256 * q;
            int r = i >> 3, cc = (i & 7) * 4;
            float4 v = *reinterpret_cast<const float4*>(&A[(size_t)(bm + r) * K + k0 + cc]);
            uint2 lo, hi = split_pack(v, lo);
            *reinterpret_cast<uint2*>(&Ahi[r][cc]) = hi;
            *reinterpret_cast<uint2*>(&Alo[r][cc]) = lo;
        }
        #pragma unroll
        for (int q = 0; q < 2; q++) {
            int i = t + 256 * q;
            int r = i >> 4, cc = (i & 15) * 4;
            float4 v = *reinterpret_cast<const float4*>(&B[(size_t)(k0 + r) * N + bn + cc]);
            uint2 lo, hi = split_pack(v, lo);
            *reinterpret_cast<uint2*>(&Bhi[r][cc]) = hi;
            *reinterpret_cast<uint2*>(&Blo[r][cc]) = lo;
        }
        __syncthreads();

        #pragma unroll
        for (int kk = 0; kk < 2; kk++) {
            uint32_t ah[2][4], al[2][4], bh[4][2], bl[4][2];
            #pragma unroll
            for (int mf = 0; mf < 2; mf++) {
                ldsm_x4(ah[mf][0], ah[mf][1], ah[mf][2], ah[mf][3],
                        smem_u32(&Ahi[wm + mf * 16 + la][kk * 16 + lb * 8]));
                ldsm_x4(al[mf][0], al[mf][1], al[mf][2], al[mf][3],
                        smem_u32(&Alo[wm + mf * 16 + la][kk * 16 + lb * 8]));
            }
            #pragma unroll
            for (int g = 0; g < 2; g++) {
                ldsm_x4_t(bh[g*2][0], bh[g*2][1], bh[g*2+1][0], bh[g*2+1][1],
                          smem_u32(&Bhi[kk * 16 + la][wn + g * 16 + lb * 8]));
                ldsm_x4_t(bl[g*2][0], bl[g*2][1], bl[g*2+1][0], bl[g*2+1][1],
                          smem_u32(&Blo[kk * 16 + la][wn + g * 16 + lb * 8]));
            }
            #pragma unroll
            for (int mf = 0; mf < 2; mf++)
                #pragma unroll
                for (int nf = 0; nf < 4; nf++) {
                    mma16816(acc[mf][nf], ah[mf], bh[nf]);
                    mma16816(acc[mf][nf], ah[mf], bl[nf]);
                    mma16816(acc[mf][nf], al[mf], bh[nf]);
                }
        }
        __syncthreads();
    }

    #pragma unroll
    for (int mf = 0; mf < 2; mf++)
        #pragma unroll
        for (int nf = 0; nf < 4; nf++) {
            int gm = bm + wm + mf * 16 + (lane >> 2);
            int gn = bn + wn + nf * 8 + (lane & 3) * 2;
            float* c = acc[mf][nf];
            *reinterpret_cast<float2*>(&C[(size_t)gm * N + gn])       = make_float2(c[0], c[1]);
            *reinterpret_cast<float2*>(&C[(size_t)(gm + 8) * N + gn]) = make_float2(c[2], c[3]);
        }
}

// ---------------- K3: HMMA GEMM, A fp16 direct, B fp32 split -> fp16 --------
__global__ __launch_bounds__(256) void hgemm_a16(
    const __half* __restrict__ A, const float* __restrict__ B,
    __half* __restrict__ Ch, int M, int K, int N)
{
    __shared__ __align__(16) __half Ahi[HBM][HBK + 8];
    __shared__ __align__(16) __half Bhi[HBK][HBN + 8];
    __shared__ __align__(16) __half Blo[HBK][HBN + 8];

    const int t    = threadIdx.x;
    const int wid  = t >> 5, lane = t & 31;
    const int wm   = (wid & 3) * 32;
    const int wn   = (wid >> 2) * 32;
    const int bm   = blockIdx.y * HBM;
    const int bn   = blockIdx.x * HBN;

    float acc[2][4][4];
    #pragma unroll
    for (int i = 0; i < 2; i++)
        #pragma unroll
        for (int j = 0; j < 4; j++)
            #pragma unroll
            for (int q = 0; q < 4; q++) acc[i][j][q] = 0.f;

    const int la = lane & 15, lb = lane >> 4;

    for (int k0 = 0; k0 < K; k0 += HBK) {
        #pragma unroll
        for (int q = 0; q < 2; q++) {
            int i = t + 256 * q;
            int r = i >> 2, c8 = (i & 3) * 8;
            uint4 v = *reinterpret_cast<const uint4*>(&A[(size_t)(bm + r) * K + k0 + c8]);
            *reinterpret_cast<uint4*>(&Ahi[r][c8]) = v;
        }
        #pragma unroll
        for (int q = 0; q < 2; q++) {
            int i = t + 256 * q;
            int r = i >> 4, cc = (i & 15) * 4;
            float4 v = *reinterpret_cast<const float4*>(&B[(size_t)(k0 + r) * N + bn + cc]);
            uint2 lo, hi = split_pack(v, lo);
            *reinterpret_cast<uint2*>(&Bhi[r][cc]) = hi;
            *reinterpret_cast<uint2*>(&Blo[r][cc]) = lo;
        }
        __syncthreads();

        #pragma unroll
        for (int kk = 0; kk < 2; kk++) {
            uint32_t ah[2][4], bh[4][2], bl[4][2];
            #pragma unroll
            for (int mf = 0; mf < 2; mf++)
                ldsm_x4(ah[mf][0], ah[mf][1], ah[mf][2], ah[mf][3],
                        smem_u32(&Ahi[wm + mf * 16 + la][kk * 16 + lb * 8]));
            #pragma unroll
            for (int g = 0; g < 2; g++) {
                ldsm_x4_t(bh[g*2][0], bh[g*2][1], bh[g*2+1][0], bh[g*2+1][1],
                          smem_u32(&Bhi[kk * 16 + la][wn + g * 16 + lb * 8]));
                ldsm_x4_t(bl[g*2][0], bl[g*2][1], bl[g*2+1][0], bl[g*2+1][1],
                          smem_u32(&Blo[kk * 16 + la][wn + g * 16 + lb * 8]));
            }
            #pragma unroll
            for (int mf = 0; mf < 2; mf++)
                #pragma unroll
                for (int nf = 0; nf < 4; nf++) {
                    mma16816(acc[mf][nf], ah[mf], bh[nf]);
                    mma16816(acc[mf][nf], ah[mf], bl[nf]);
                }
        }
        __syncthreads();
    }

    #pragma unroll
    for (int mf = 0; mf < 2; mf++)
        #pragma unroll
        for (int nf = 0; nf < 4; nf++) {
            int gm = bm + wm + mf * 16 + (lane >> 2);
            int gn = bn + wn + nf * 8 + (lane & 3) * 2;
            float* c = acc[mf][nf];
            *reinterpret_cast<__half2*>(&Ch[(size_t)gm * N + gn])       = __floats2half2_rn(c[0], c[1]);
            *reinterpret_cast<__half2*>(&Ch[(size_t)(gm + 8) * N + gn]) = __floats2half2_rn(c[2], c[3]);
        }
}

// ---------------- KV: v1 = Wa @ a1, v2 = Wa @ a2 ----------------------------
__global__ __launch_bounds__(256) void kv_v12(const float* __restrict__ Wa,
                                              const float* __restrict__ a_vec)
{
    __shared__ float a1[NHID], a2[NHID];
    const int t = threadIdx.x;
    a1[t] = a_vec[t];
    a2[t] = a_vec[NHID + t];
    __syncthreads();
    const float* wr = Wa + (size_t)t * NHID;
    float s1 = 0.f, s2 = 0.f;
    #pragma unroll 8
    for (int j = 0; j < NHID; j++) {
        float w = wr[j];
        s1 = fmaf(w, a1[j], s1);
        s2 = fmaf(w, a2[j], s2);
    }
    g_v1[t] = s1;
    g_v2[t] = s2;
}

// ---------------- K2: h1 = relu(gather-sum(fp32 xW1) + b1) ------------------
__global__ __launch_bounds__(256) void k2_spmm_relu(const float* __restrict__ b1,
                                                    float* __restrict__ d_out)
{
    const int row = blockIdx.x;
    const int t   = threadIdx.x;
    const int c4  = t & 63;
    const int par = t >> 6;
    __shared__ __align__(16) float part[4][256];
    __shared__ __align__(16) int   nboff[CAP];
    const int cnt = g_cnt[row];
    for (int i = t; i < cnt; i += 256) nboff[i] = g_nbr[(size_t)row * CAP + i] << 10;
    __syncthreads();

    const char* base = (const char*)g_xW1;
    const int c16 = c4 * 16;
    float ax = 0.f, ay = 0.f, az = 0.f, aw = 0.f;
    int i = par;
    for (; i + 4 < cnt; i += 8) {
        float4 v0 = *reinterpret_cast<const float4*>(base + nboff[i]     + c16);
        float4 v1 = *reinterpret_cast<const float4*>(base + nboff[i + 4] + c16);
        ax += v0.x + v1.x; ay += v0.y + v1.y;
        az += v0.z + v1.z; aw += v0.w + v1.w;
    }
    for (; i < cnt; i += 4) {
        float4 v = *reinterpret_cast<const float4*>(base + nboff[i] + c16);
        ax += v.x; ay += v.y; az += v.z; aw += v.w;
    }
    *reinterpret_cast<float4*>(&part[par][c4 * 4]) = make_float4(ax, ay, az, aw);
    __syncthreads();
    if (t < 128) {
        const int c2 = t;
        float sx = (part[0][2*c2]   + part[1][2*c2])   + (part[2][2*c2]   + part[3][2*c2]);
        float sy = (part[0][2*c2+1] + part[1][2*c2+1]) + (part[2][2*c2+1] + part[3][2*c2+1]);
        float2 b = reinterpret_cast<const float2*>(b1)[c2];
        float vx = fmaxf(sx + b.x, 0.f);
        float vy = fmaxf(sy + b.y, 0.f);
        reinterpret_cast<__half2*>(g_h1h + (size_t)row * NHID)[c2] = __floats2half2_rn(vx, vy);
        reinterpret_cast<float2*>(d_out + CONCAT_OFF + (size_t)row * CONCAT_W)[c2] = make_float2(vx, vy);
    }
}

// ---------------- K4: f1 = h1 @ v1, f2 = h1 @ v2 (h1 fp16) ------------------
__global__ void k4_f12() {
    const int row = blockIdx.x * 8 + threadIdx.y;
    const int lane = threadIdx.x;
    float s1 = 0.f, s2 = 0.f;
    const __half2* h = reinterpret_cast<const __half2*>(g_h1h + (size_t)row * NHID);
    #pragma unroll
    for (int c2 = lane; c2 < 128; c2 += 32) {
        float2 f = __half22float2(h[c2]);
        s1 = fmaf(f.x, g_v1[2*c2], fmaf(f.y, g_v1[2*c2+1], s1));
        s2 = fmaf(f.x, g_v2[2*c2], fmaf(f.y, g_v2[2*c2+1], s2));
    }
    s1 = warpSum(s1); s2 = warpSum(s2);
    if (lane == 0) { g_f1[row] = s1; g_f2[row] = s2; }
}

// ---------------- K5: masked softmax + sparse scatter + h' + elu ------------
__global__ __launch_bounds__(256) void k5_attention(float* __restrict__ d_out)
{
    const int row = blockIdx.x;
    const int t   = threadIdx.x;
    const int lane = t & 31, wid = t >> 5;
    __shared__ __align__(16) float part[8][NHID];
    __shared__ __align__(16) int   nboff[CAP];
    __shared__ int   nb[CAP];
    __shared__ float av[CAP];
    __shared__ float red[8];

    const int cnt = min(g_cnt[row], CAP);
    for (int i = t; i < cnt; i += 256) {
        int n = g_nbr[(size_t)row * CAP + i];
        nb[i] = n;
        nboff[i] = n << 9;
    }
    __syncthreads();

    const float fi = g_f1[row];
    float e = -1e30f;
    if (t < cnt) {
        float z = fi + g_f2[nb[t]];
        e = z > 0.f ? z : 0.01f * z;
    }
    float wm = warpMax(e);
    if (lane == 0) red[wid] = wm;
    __syncthreads();
    if (wid == 0) {
        float v = (lane < 8) ? red[lane] : -1e30f;
        v = warpMax(v);
        if (lane == 0) red[0] = v;
    }
    __syncthreads();
    const float m = red[0];
    __syncthreads();
    float p = (t < cnt) ? expf(e - m) : 0.f;
    float ws = warpSum(p);
    if (lane == 0) red[wid] = ws;
    __syncthreads();
    if (wid == 0) {
        float v = (lane < 8) ? red[lane] : 0.f;
        v = warpSum(v);
        if (lane == 0) red[0] = v;
    }
    __syncthreads();
    const float inv_s = 1.f / red[0];
    if (t < cnt) {
        float a = p * inv_s;
        av[t] = a;
        d_out[ATT_OFF + (size_t)row * NN + nb[t]] = a;
    }
    __syncthreads();

    // h_prime[row] = sum_j av[j] * Whh[nb[j]]  (fp16 table, uint4 = 8 cols)
    const char* base = (const char*)g_Whh;
    const int c16 = lane * 16;
    float a[8] = {0.f, 0.f, 0.f, 0.f, 0.f, 0.f, 0.f, 0.f};
    int i = wid;
    for (; i + 8 < cnt; i += 16) {
        float s0 = av[i], s1 = av[i + 8];
        uint4 v0 = *reinterpret_cast<const uint4*>(base + nboff[i]     + c16);
        uint4 v1 = *reinterpret_cast<const uint4*>(base + nboff[i + 8] + c16);
        acc8(v0, s0, a); acc8(v1, s1, a);
    }
    for (; i < cnt; i += 8) {
        uint4 v = *reinterpret_cast<const uint4*>(base + nboff[i] + c16);
        acc8(v, av[i], a);
    }
    *reinterpret_cast<float4*>(&part[wid][lane * 8])     = make_float4(a[0], a[1], a[2], a[3]);
    *reinterpret_cast<float4*>(&part[wid][lane * 8 + 4]) = make_float4(a[4], a[5], a[6], a[7]);
    __syncthreads();

    if (t < 128) {
        const int c2 = t;
        float sx = 0.f, sy = 0.f;
        #pragma unroll
        for (int p = 0; p < 8; p++) { sx += part[p][2*c2]; sy += part[p][2*c2+1]; }
        float ox = sx > 0.f ? sx : (expf(sx) - 1.f);
        float oy = sy > 0.f ? sy : (expf(sy) - 1.f);
        reinterpret_cast<float2*>(g_aout + (size_t)row * NHID)[c2] = make_float2(ox, oy);
    }
}

// ---------------- K6: t16 = a_out @ W3 --------------------------------------
__global__ __launch_bounds__(256) void k6_gemm3(const float* __restrict__ W3)
{
    __shared__ float As[16][257];
    __shared__ float Ws[NHID][16];
    const int t = threadIdx.x;
    const int row0 = blockIdx.x * 16;

    for (int idx = t; idx < 16 * NHID; idx += 256)
        As[idx >> 8][idx & 255] = g_aout[(size_t)(row0 + (idx >> 8)) * NHID + (idx & 255)];
    for (int idx = t; idx < NHID * 16; idx += 256)
        Ws[idx >> 4][idx & 15] = W3[idx];
    __syncthreads();

    const int r = t >> 4, c = t & 15;
    float acc = 0.f;
    #pragma unroll 8
    for (int k = 0; k < NHID; k++) acc = fmaf(As[r][k], Ws[k][c], acc);
    g_t16[(size_t)(row0 + r) * NCLASS + c] = acc;
}

// ---------------- K7: out = gather(t16) + b3 -> sigmoid + concat ------------
__global__ __launch_bounds__(256) void k7_final(const float* __restrict__ b3,
                                                float* __restrict__ d_out)
{
    const int t = threadIdx.x;
    const int row = blockIdx.x * 16 + (t >> 4);
    const int c = t & 15;
    const int cnt = g_cnt[row];
    const int* nbr = g_nbr + (size_t)row * CAP;

    float acc = 0.f;
    int i = 0;
    for (; i + 4 <= cnt; i += 4) {
        int n0 = nbr[i], n1 = nbr[i + 1], n2 = nbr[i + 2], n3 = nbr[i + 3];
        float v0 = g_t16[(size_t)n0 * NCLASS + c];
        float v1 = g_t16[(size_t)n1 * NCLASS + c];
        float v2 = g_t16[(size_t)n2 * NCLASS + c];
        float v3 = g_t16[(size_t)n3 * NCLASS + c];
        acc += (v0 + v1) + (v2 + v3);
    }
    for (; i < cnt; i++) acc += g_t16[(size_t)nbr[i] * NCLASS + c];

    float o = acc + b3[c];
    d_out[OUT0_OFF + (size_t)row * NCLASS + c] = 1.f / (1.f + expf(-o));
    d_out[CONCAT_OFF + (size_t)row * CONCAT_W + NHID + c] = o;
}

// ---------------- launch -----------------------------------------------------
extern "C" void kernel_launch(void* const* d_in, const int* in_sizes, int n_in,
                              void* d_out_v, int out_size)
{
    const float* x     = (const float*)d_in[0];
    const int*   adj   = (const int*)  d_in[1];
    const float* W1    = (const float*)d_in[2];
    const float* b1    = (const float*)d_in[3];
    const float* Wa    = (const float*)d_in[4];
    const float* a_vec = (const float*)d_in[5];
    const float* W3    = (const float*)d_in[6];
    const float* b3    = (const float*)d_in[7];
    float* d_out = (float*)d_out_v;

    float  *p_xW1;
    __half *p_h1h, *p_Whh;
    cudaGetSymbolAddress((void**)&p_xW1, g_xW1);
    cudaGetSymbolAddress((void**)&p_h1h, g_h1h);
    cudaGetSymbolAddress((void**)&p_Whh, g_Whh);

    static cudaStream_t sAdj = nullptr, sSet = nullptr, sV = nullptr;
    static cudaEvent_t evRoot = nullptr, evAdj = nullptr, evSet = nullptr,
                       evH1 = nullptr, evF = nullptr;
    if (!sAdj) {
        cudaStreamCreateWithFlags(&sAdj, cudaStreamNonBlocking);
        cudaStreamCreateWithFlags(&sSet, cudaStreamNonBlocking);
        cudaStreamCreateWithFlags(&sV,   cudaStreamNonBlocking);
        cudaEventCreateWithFlags(&evRoot, cudaEventDisableTiming);
        cudaEventCreateWithFlags(&evAdj,  cudaEventDisableTiming);
        cudaEventCreateWithFlags(&evSet,  cudaEventDisableTiming);
        cudaEventCreateWithFlags(&evH1,   cudaEventDisableTiming);
        cudaEventCreateWithFlags(&evF,    cudaEventDisableTiming);
    }
    cudaStream_t s0 = (cudaStream_t)0;

    cudaEventRecord(evRoot, s0);
    cudaStreamWaitEvent(sAdj, evRoot, 0);
    cudaStreamWaitEvent(sSet, evRoot, 0);
    cudaStreamWaitEvent(sV,   evRoot, 0);

    // side A: adjacency scan
    k0_scan_adj<<<NN, 256, 0, sAdj>>>(adj);
    cudaEventRecord(evAdj, sAdj);

    // side B: zero attention region
    cudaMemsetAsync(d_out + ATT_OFF, 0, (size_t)NN * NN * sizeof(float), sSet);
    cudaEventRecord(evSet, sSet);

    // side C: v1/v2
    kv_v12<<<1, 256, 0, sV>>>(Wa, a_vec);

    // main: K1 -> fp32 table (feat accuracy)
    hgemm_split<<<dim3(NHID / HBN, NN / HBM), 256, 0, s0>>>(x, W1, p_xW1, NN, NFEAT, NHID);

    // join adjacency -> K2
    cudaStreamWaitEvent(s0, evAdj, 0);
    k2_spmm_relu<<<NN, 256, 0, s0>>>(b1, d_out);
    cudaEventRecord(evH1, s0);

    // side C: f1/f2 (parallel with K3)
    cudaStreamWaitEvent(sV, evH1, 0);
    k4_f12<<<NN / 8, dim3(32, 8), 0, sV>>>();
    cudaEventRecord(evF, sV);

    // main: K3 -> fp16 Whh (halves K5 gather bytes + K3 store bytes)
    hgemm_a16<<<dim3(NHID / HBN, NN / HBM), 256, 0, s0>>>(p_h1h, Wa, p_Whh, NN, NHID, NHID);

    // join -> K5
    cudaStreamWaitEvent(s0, evF, 0);
    cudaStreamWaitEvent(s0, evSet, 0);
    k5_attention<<<NN, 256, 0, s0>>>(d_out);

    k6_gemm3<<<NN / 16, 256, 0, s0>>>(W3);
    k7_final<<<NN / 16, 256, 0, s0>>>(b3, d_out);
}

// round 16
// speedup vs baseline: 1.0910x; 1.0161x over previous
#include <cuda_runtime.h>
#include <cuda_fp16.h>
#include <cstdint>

#define NN     8192
#define NFEAT  512
#define NHID   256
#define NCLASS 16
#define CAP    256

#define OUT0_OFF    0
#define ATT_OFF     (NN*NCLASS)
#define CONCAT_OFF  (ATT_OFF + (size_t)NN*NN)
#define CONCAT_W    (NHID + NCLASS)

// ---------------- scratch (16B-aligned) -------------------------------------
__device__ __align__(16) __half g_xW1h[NN*NHID];   // fp16 gather table (K2)
__device__ __align__(16) float  g_h1  [NN*NHID];   // fp32 h1 (K3 A, K4)
__device__ __align__(16) __half g_Whh [NN*NHID];   // fp16 gather table (K5)
__device__ __align__(16) float  g_aout[NN*NHID];
__device__ __align__(16) float  g_f1  [NN];
__device__ __align__(16) float  g_f2  [NN];
__device__ __align__(16) float  g_v1  [NHID];
__device__ __align__(16) float  g_v2  [NHID];
__device__ __align__(16) float  g_t16 [NN*NCLASS];
__device__ __align__(16) int    g_nbr [NN*CAP];
__device__ __align__(16) int    g_cnt [NN];

// ---------------- helpers ---------------------------------------------------
__device__ __forceinline__ float warpMax(float v) {
    #pragma unroll
    for (int o = 16; o > 0; o >>= 1) v = fmaxf(v, __shfl_xor_sync(0xffffffffu, v, o));
    return v;
}
__device__ __forceinline__ float warpSum(float v) {
    #pragma unroll
    for (int o = 16; o > 0; o >>= 1) v += __shfl_xor_sync(0xffffffffu, v, o);
    return v;
}
__device__ __forceinline__ uint32_t smem_u32(const void* p) {
    return (uint32_t)__cvta_generic_to_shared(p);
}
__device__ __forceinline__ void ldsm_x4(uint32_t& r0, uint32_t& r1, uint32_t& r2, uint32_t& r3, uint32_t a) {
    asm volatile("ldmatrix.sync.aligned.m8n8.x4.shared.b16 {%0,%1,%2,%3}, [%4];"
                 : "=r"(r0), "=r"(r1), "=r"(r2), "=r"(r3) : "r"(a));
}
__device__ __forceinline__ void ldsm_x4_t(uint32_t& r0, uint32_t& r1, uint32_t& r2, uint32_t& r3, uint32_t a) {
    asm volatile("ldmatrix.sync.aligned.m8n8.x4.trans.shared.b16 {%0,%1,%2,%3}, [%4];"
                 : "=r"(r0), "=r"(r1), "=r"(r2), "=r"(r3) : "r"(a));
}
__device__ __forceinline__ void mma16816(float* c, const uint32_t* a, const uint32_t* b) {
    asm volatile(
        "mma.sync.aligned.m16n8k16.row.col.f32.f16.f16.f32 "
        "{%0,%1,%2,%3},{%4,%5,%6,%7},{%8,%9},{%0,%1,%2,%3};"
        : "+f"(c[0]), "+f"(c[1]), "+f"(c[2]), "+f"(c[3])
        : "r"(a[0]), "r"(a[1]), "r"(a[2]), "r"(a[3]), "r"(b[0]), "r"(b[1]));
}
__device__ __forceinline__ uint2 split_pack(float4 v, uint2& lo) {
    __half hx = __float2half_rn(v.x), hy = __float2half_rn(v.y);
    __half hz = __float2half_rn(v.z), hw = __float2half_rn(v.w);
    __half2 hi01 = __halves2half2(hx, hy), hi23 = __halves2half2(hz, hw);
    __half2 lo01 = __floats2half2_rn(v.x - __half2float(hx), v.y - __half2float(hy));
    __half2 lo23 = __floats2half2_rn(v.z - __half2float(hz), v.w - __half2float(hw));
    uint2 hi;
    hi.x = *reinterpret_cast<uint32_t*>(&hi01); hi.y = *reinterpret_cast<uint32_t*>(&hi23);
    lo.x = *reinterpret_cast<uint32_t*>(&lo01); lo.y = *reinterpret_cast<uint32_t*>(&lo23);
    return hi;
}
// accumulate 8 cols from one uint4 of halves
__device__ __forceinline__ void acc8(const uint4 v, float s, float* a) {
    const __half2* h = reinterpret_cast<const __half2*>(&v);
    #pragma unroll
    for (int j = 0; j < 4; j++) {
        float2 f = __half22float2(h[j]);
        a[2*j]   = fmaf(s, f.x, a[2*j]);
        a[2*j+1] = fmaf(s, f.y, a[2*j+1]);
    }
}
__device__ __forceinline__ void add8(const uint4 v, float* a) {
    const __half2* h = reinterpret_cast<const __half2*>(&v);
    #pragma unroll
    for (int j = 0; j < 4; j++) {
        float2 f = __half22float2(h[j]);
        a[2*j]   += f.x;
        a[2*j+1] += f.y;
    }
}

// ---------------- K0: adjacency scan (ballot/shfl, 2 barriers) --------------
__global__ void k0_scan_adj(const int* __restrict__ adj) {
    const int row = blockIdx.x;
    const int t   = threadIdx.x;
    const int lane = t & 31, wid = t >> 5;
    __shared__ int warpTot[8], warpOff[8];

    const int4* arow = reinterpret_cast<const int4*>(adj + (size_t)row * NN);
    int4 vv[8];
    int c = 0;
    #pragma unroll
    for (int q = 0; q < 8; q++) {
        vv[q] = arow[t * 8 + q];
        c += (vv[q].x != 0) + (vv[q].y != 0) + (vv[q].z != 0) + (vv[q].w != 0);
    }
    int sc = c;
    #pragma unroll
    for (int d = 1; d < 32; d <<= 1) {
        int o = __shfl_up_sync(0xffffffffu, sc, d);
        if (lane >= d) sc += o;
    }
    if (lane == 31) warpTot[wid] = sc;
    __syncthreads();
    if (t == 0) {
        int s = 0;
        #pragma unroll
        for (int w = 0; w < 8; w++) { warpOff[w] = s; s += warpTot[w]; }
        g_cnt[row] = min(s, CAP);
    }
    __syncthreads();

    int w = warpOff[wid] + sc - c;
    int* dst = g_nbr + (size_t)row * CAP;
    #pragma unroll
    for (int q = 0; q < 8; q++) {
        int base = t * 32 + q * 4;
        if (vv[q].x && w < CAP) dst[w++] = base + 0;
        if (vv[q].y && w < CAP) dst[w++] = base + 1;
        if (vv[q].z && w < CAP) dst[w++] = base + 2;
        if (vv[q].w && w < CAP) dst[w++] = base + 3;
    }
}

// ---------------- K1/K3: split-fp16 HMMA GEMM (3-pass) -> fp16 table --------
#define HBM 128
#define HBN 64
#define HBK 32
__global__ __launch_bounds__(256) void hgemm_split(
    const float* __restrict__ A, const float* __restrict__ B,
    __half* __restrict__ Ch, int M, int K, int N)
{
    __shared__ __align__(16) __half Ahi[HBM][HBK + 8];
    __shared__ __align__(16) __half Alo[HBM][HBK + 8];
    __shared__ __align__(16) __half Bhi[HBK][HBN + 8];
    __shared__ __align__(16) __half Blo[HBK][HBN + 8];

    const int t    = threadIdx.x;
    const int wid  = t >> 5, lane = t & 31;
    const int wm   = (wid & 3) * 32;
    const int wn   = (wid >> 2) * 32;
    const int bm   = blockIdx.y * HBM;
    const int bn   = blockIdx.x * HBN;

    float acc[2][4][4];
    #pragma unroll
    for (int i = 0; i < 2; i++)
        #pragma unroll
        for (int j = 0; j < 4; j++)
            #pragma unroll
            for (int q = 0; q < 4; q++) acc[i][j][q] = 0.f;

    const int la = lane & 15, lb = lane >> 4;

    for (int k0 = 0; k0 < K; k0 += HBK) {
        #pragma unroll
        for (int q = 0; q < 4; q++) {
            int i = t + 256 * q;
            int r = i >> 3, cc = (i & 7) * 4;
            float4 v = *reinterpret_cast<const float4*>(&A[(size_t)(bm + r) * K + k0 + cc]);
            uint2 lo, hi = split_pack(v, lo);
            *reinterpret_cast<uint2*>(&Ahi[r][cc]) = hi;
            *reinterpret_cast<uint2*>(&Alo[r][cc]) = lo;
        }
        #pragma unroll
        for (int q = 0; q < 2; q++) {
            int i = t + 256 * q;
            int r = i >> 4, cc = (i & 15) * 4;
            float4 v = *reinterpret_cast<const float4*>(&B[(size_t)(k0 + r) * N + bn + cc]);
            uint2 lo, hi = split_pack(v, lo);
            *reinterpret_cast<uint2*>(&Bhi[r][cc]) = hi;
            *reinterpret_cast<uint2*>(&Blo[r][cc]) = lo;
        }
        __syncthreads();

        #pragma unroll
        for (int kk = 0; kk < 2; kk++) {
            uint32_t ah[2][4], al[2][4], bh[4][2], bl[4][2];
            #pragma unroll
            for (int mf = 0; mf < 2; mf++) {
                ldsm_x4(ah[mf][0], ah[mf][1], ah[mf][2], ah[mf][3],
                        smem_u32(&Ahi[wm + mf * 16 + la][kk * 16 + lb * 8]));
                ldsm_x4(al[mf][0], al[mf][1], al[mf][2], al[mf][3],
                        smem_u32(&Alo[wm + mf * 16 + la][kk * 16 + lb * 8]));
            }
            #pragma unroll
            for (int g = 0; g < 2; g++) {
                ldsm_x4_t(bh[g*2][0], bh[g*2][1], bh[g*2+1][0], bh[g*2+1][1],
                          smem_u32(&Bhi[kk * 16 + la][wn + g * 16 + lb * 8]));
                ldsm_x4_t(bl[g*2][0], bl[g*2][1], bl[g*2+1][0], bl[g*2+1][1],
                          smem_u32(&Blo[kk * 16 + la][wn + g * 16 + lb * 8]));
            }
            #pragma unroll
            for (int mf = 0; mf < 2; mf++)
                #pragma unroll
                for (int nf = 0; nf < 4; nf++) {
                    mma16816(acc[mf][nf], ah[mf], bh[nf]);
                    mma16816(acc[mf][nf], ah[mf], bl[nf]);
                    mma16816(acc[mf][nf], al[mf], bh[nf]);
                }
        }
        __syncthreads();
    }

    #pragma unroll
    for (int mf = 0; mf < 2; mf++)
        #pragma unroll
        for (int nf = 0; nf < 4; nf++) {
            int gm = bm + wm + mf * 16 + (lane >> 2);
            int gn = bn + wn + nf * 8 + (lane & 3) * 2;
            float* c = acc[mf][nf];
            *reinterpret_cast<__half2*>(&Ch[(size_t)gm * N + gn])       = __floats2half2_rn(c[0], c[1]);
            *reinterpret_cast<__half2*>(&Ch[(size_t)(gm + 8) * N + gn]) = __floats2half2_rn(c[2], c[3]);
        }
}

// ---------------- KV: v1 = Wa @ a1, v2 = Wa @ a2 ----------------------------
__global__ __launch_bounds__(256) void kv_v12(const float* __restrict__ Wa,
                                              const float* __restrict__ a_vec)
{
    __shared__ float a1[NHID], a2[NHID];
    const int t = threadIdx.x;
    a1[t] = a_vec[t];
    a2[t] = a_vec[NHID + t];
    __syncthreads();
    const float* wr = Wa + (size_t)t * NHID;
    float s1 = 0.f, s2 = 0.f;
    #pragma unroll 8
    for (int j = 0; j < NHID; j++) {
        float w = wr[j];
        s1 = fmaf(w, a1[j], s1);
        s2 = fmaf(w, a2[j], s2);
    }
    g_v1[t] = s1;
    g_v2[t] = s2;
}

// ---------------- K2: h1 = relu(gather-sum(fp16 xW1) + b1) -> fp32 h1 -------
// 8 warps = parities over neighbors, lane = 8-col group (uint4 fp16 loads).
__global__ __launch_bounds__(256) void k2_spmm_relu(const float* __restrict__ b1,
                                                    float* __restrict__ d_out)
{
    const int row = blockIdx.x;
    const int t   = threadIdx.x;
    const int lane = t & 31, wid = t >> 5;
    __shared__ __align__(16) float part[8][NHID];
    __shared__ __align__(16) int   nboff[CAP];
    const int cnt = g_cnt[row];
    for (int i = t; i < cnt; i += 256) nboff[i] = g_nbr[(size_t)row * CAP + i] << 9;
    __syncthreads();

    const char* base = (const char*)g_xW1h;
    const int c16 = lane * 16;
    float a[8] = {0.f, 0.f, 0.f, 0.f, 0.f, 0.f, 0.f, 0.f};
    int i = wid;
    for (; i + 8 < cnt; i += 16) {
        uint4 v0 = *reinterpret_cast<const uint4*>(base + nboff[i]     + c16);
        uint4 v1 = *reinterpret_cast<const uint4*>(base + nboff[i + 8] + c16);
        add8(v0, a); add8(v1, a);
    }
    for (; i < cnt; i += 8) {
        uint4 v = *reinterpret_cast<const uint4*>(base + nboff[i] + c16);
        add8(v, a);
    }
    *reinterpret_cast<float4*>(&part[wid][lane * 8])     = make_float4(a[0], a[1], a[2], a[3]);
    *reinterpret_cast<float4*>(&part[wid][lane * 8 + 4]) = make_float4(a[4], a[5], a[6], a[7]);
    __syncthreads();

    if (t < 128) {
        const int c2 = t;
        float sx = 0.f, sy = 0.f;
        #pragma unroll
        for (int p = 0; p < 8; p++) { sx += part[p][2*c2]; sy += part[p][2*c2+1]; }
        float2 b = reinterpret_cast<const float2*>(b1)[c2];
        float vx = fmaxf(sx + b.x, 0.f);
        float vy = fmaxf(sy + b.y, 0.f);
        reinterpret_cast<float2*>(g_h1 + (size_t)row * NHID)[c2] = make_float2(vx, vy);
        reinterpret_cast<float2*>(d_out + CONCAT_OFF + (size_t)row * CONCAT_W)[c2] = make_float2(vx, vy);
    }
}

// ---------------- K4: f1 = h1 @ v1, f2 = h1 @ v2 (fp32 h1) ------------------
__global__ void k4_f12() {
    const int row = blockIdx.x * 8 + threadIdx.y;
    const int lane = threadIdx.x;
    float s1 = 0.f, s2 = 0.f;
    const float* h = g_h1 + (size_t)row * NHID;
    #pragma unroll
    for (int c = lane; c < NHID; c += 32) {
        float w = h[c];
        s1 = fmaf(w, g_v1[c], s1);
        s2 = fmaf(w, g_v2[c], s2);
    }
    s1 = warpSum(s1); s2 = warpSum(s2);
    if (lane == 0) { g_f1[row] = s1; g_f2[row] = s2; }
}

// ---------------- K5: masked softmax + sparse scatter + h' + elu ------------
__global__ __launch_bounds__(256) void k5_attention(float* __restrict__ d_out)
{
    const int row = blockIdx.x;
    const int t   = threadIdx.x;
    const int lane = t & 31, wid = t >> 5;
    __shared__ __align__(16) float part[8][NHID];
    __shared__ __align__(16) int   nboff[CAP];
    __shared__ int   nb[CAP];
    __shared__ float av[CAP];
    __shared__ float red[8];

    const int cnt = min(g_cnt[row], CAP);
    for (int i = t; i < cnt; i += 256) {
        int n = g_nbr[(size_t)row * CAP + i];
        nb[i] = n;
        nboff[i] = n << 9;
    }
    __syncthreads();

    const float fi = g_f1[row];
    float e = -1e30f;
    if (t < cnt) {
        float z = fi + g_f2[nb[t]];
        e = z > 0.f ? z : 0.01f * z;
    }
    float wm = warpMax(e);
    if (lane == 0) red[wid] = wm;
    __syncthreads();
    if (wid == 0) {
        float v = (lane < 8) ? red[lane] : -1e30f;
        v = warpMax(v);
        if (lane == 0) red[0] = v;
    }
    __syncthreads();
    const float m = red[0];
    __syncthreads();
    float p = (t < cnt) ? expf(e - m) : 0.f;
    float ws = warpSum(p);
    if (lane == 0) red[wid] = ws;
    __syncthreads();
    if (wid == 0) {
        float v = (lane < 8) ? red[lane] : 0.f;
        v = warpSum(v);
        if (lane == 0) red[0] = v;
    }
    __syncthreads();
    const float inv_s = 1.f / red[0];
    if (t < cnt) {
        float a = p * inv_s;
        av[t] = a;
        d_out[ATT_OFF + (size_t)row * NN + nb[t]] = a;
    }
    __syncthreads();

    // h_prime[row] = sum_j av[j] * Whh[nb[j]]  (fp16 table, uint4 = 8 cols)
    const char* base = (const char*)g_Whh;
    const int c16 = lane * 16;
    float a[8] = {0.f, 0.f, 0.f, 0.f, 0.f, 0.f, 0.f, 0.f};
    int i = wid;
    for (; i + 8 < cnt; i += 16) {
        float s0 = av[i], s1 = av[i + 8];
        uint4 v0 = *reinterpret_cast<const uint4*>(base + nboff[i]     + c16);
        uint4 v1 = *reinterpret_cast<const uint4*>(base + nboff[i + 8] + c16);
        acc8(v0, s0, a); acc8(v1, s1, a);
    }
    for (; i < cnt; i += 8) {
        uint4 v = *reinterpret_cast<const uint4*>(base + nboff[i] + c16);
        acc8(v, av[i], a);
    }
    *reinterpret_cast<float4*>(&part[wid][lane * 8])     = make_float4(a[0], a[1], a[2], a[3]);
    *reinterpret_cast<float4*>(&part[wid][lane * 8 + 4]) = make_float4(a[4], a[5], a[6], a[7]);
    __syncthreads();

    if (t < 128) {
        const int c2 = t;
        float sx = 0.f, sy = 0.f;
        #pragma unroll
        for (int p = 0; p < 8; p++) { sx += part[p][2*c2]; sy += part[p][2*c2+1]; }
        float ox = sx > 0.f ? sx : (expf(sx) - 1.f);
        float oy = sy > 0.f ? sy : (expf(sy) - 1.f);
        reinterpret_cast<float2*>(g_aout + (size_t)row * NHID)[c2] = make_float2(ox, oy);
    }
}

// ---------------- K6: t16 = a_out @ W3 --------------------------------------
__global__ __launch_bounds__(256) void k6_gemm3(const float* __restrict__ W3)
{
    __shared__ float As[16][257];
    __shared__ float Ws[NHID][16];
    const int t = threadIdx.x;
    const int row0 = blockIdx.x * 16;

    for (int idx = t; idx < 16 * NHID; idx += 256)
        As[idx >> 8][idx & 255] = g_aout[(size_t)(row0 + (idx >> 8)) * NHID + (idx & 255)];
    for (int idx = t; idx < NHID * 16; idx += 256)
        Ws[idx >> 4][idx & 15] = W3[idx];
    __syncthreads();

    const int r = t >> 4, c = t & 15;
    float acc = 0.f;
    #pragma unroll 8
    for (int k = 0; k < NHID; k++) acc = fmaf(As[r][k], Ws[k][c], acc);
    g_t16[(size_t)(row0 + r) * NCLASS + c] = acc;
}

// ---------------- K7: out = gather(t16) + b3 -> sigmoid + concat ------------
__global__ __launch_bounds__(256) void k7_final(const float* __restrict__ b3,
                                                float* __restrict__ d_out)
{
    const int t = threadIdx.x;
    const int row = blockIdx.x * 16 + (t >> 4);
    const int c = t & 15;
    const int cnt = g_cnt[row];
    const int* nbr = g_nbr + (size_t)row * CAP;

    float acc = 0.f;
    int i = 0;
    for (; i + 4 <= cnt; i += 4) {
        int n0 = nbr[i], n1 = nbr[i + 1], n2 = nbr[i + 2], n3 = nbr[i + 3];
        float v0 = g_t16[(size_t)n0 * NCLASS + c];
        float v1 = g_t16[(size_t)n1 * NCLASS + c];
        float v2 = g_t16[(size_t)n2 * NCLASS + c];
        float v3 = g_t16[(size_t)n3 * NCLASS + c];
        acc += (v0 + v1) + (v2 + v3);
    }
    for (; i < cnt; i++) acc += g_t16[(size_t)nbr[i] * NCLASS + c];

    float o = acc + b3[c];
    d_out[OUT0_OFF + (size_t)row * NCLASS + c] = 1.f / (1.f + expf(-o));
    d_out[CONCAT_OFF + (size_t)row * CONCAT_W + NHID + c] = o;
}

// ---------------- launch -----------------------------------------------------
extern "C" void kernel_launch(void* const* d_in, const int* in_sizes, int n_in,
                              void* d_out_v, int out_size)
{
    const float* x     = (const float*)d_in[0];
    const int*   adj   = (const int*)  d_in[1];
    const float* W1    = (const float*)d_in[2];
    const float* b1    = (const float*)d_in[3];
    const float* Wa    = (const float*)d_in[4];
    const float* a_vec = (const float*)d_in[5];
    const float* W3    = (const float*)d_in[6];
    const float* b3    = (const float*)d_in[7];
    float* d_out = (float*)d_out_v;

    float  *p_h1;
    __half *p_xW1h, *p_Whh;
    cudaGetSymbolAddress((void**)&p_xW1h, g_xW1h);
    cudaGetSymbolAddress((void**)&p_h1,   g_h1);
    cudaGetSymbolAddress((void**)&p_Whh,  g_Whh);

    static cudaStream_t sAdj = nullptr, sSet = nullptr, sV = nullptr;
    static cudaEvent_t evRoot = nullptr, evAdj = nullptr, evSet = nullptr,
                       evH1 = nullptr, evF = nullptr;
    if (!sAdj) {
        cudaStreamCreateWithFlags(&sAdj, cudaStreamNonBlocking);
        cudaStreamCreateWithFlags(&sSet, cudaStreamNonBlocking);
        cudaStreamCreateWithFlags(&sV,   cudaStreamNonBlocking);
        cudaEventCreateWithFlags(&evRoot, cudaEventDisableTiming);
        cudaEventCreateWithFlags(&evAdj,  cudaEventDisableTiming);
        cudaEventCreateWithFlags(&evSet,  cudaEventDisableTiming);
        cudaEventCreateWithFlags(&evH1,   cudaEventDisableTiming);
        cudaEventCreateWithFlags(&evF,    cudaEventDisableTiming);
    }
    cudaStream_t s0 = (cudaStream_t)0;

    cudaEventRecord(evRoot, s0);
    cudaStreamWaitEvent(sAdj, evRoot, 0);
    cudaStreamWaitEvent(sV,   evRoot, 0);

    // side A: adjacency scan gets DRAM read bandwidth to itself
    k0_scan_adj<<<NN, 256, 0, sAdj>>>(adj);
    cudaEventRecord(evAdj, sAdj);

    // side B: memset AFTER the adj scan -> hides under L2-bound K2/K3
    cudaStreamWaitEvent(sSet, evAdj, 0);
    cudaMemsetAsync(d_out + ATT_OFF, 0, (size_t)NN * NN * sizeof(float), sSet);
    cudaEventRecord(evSet, sSet);

    // side C: v1/v2
    kv_v12<<<1, 256, 0, sV>>>(Wa, a_vec);

    // main: K1 -> fp16 xW1 table (runs under K0)
    hgemm_split<<<dim3(NHID / HBN, NN / HBM), 256, 0, s0>>>(x, W1, p_xW1h, NN, NFEAT, NHID);

    // join adjacency -> K2 (fp16 gather, fp32 h1 out)
    cudaStreamWaitEvent(s0, evAdj, 0);
    k2_spmm_relu<<<NN, 256, 0, s0>>>(b1, d_out);
    cudaEventRecord(evH1, s0);

    // side C: f1/f2 (fp32 h1, parallel with K3)
    cudaStreamWaitEvent(sV, evH1, 0);
    k4_f12<<<NN / 8, dim3(32, 8), 0, sV>>>();
    cudaEventRecord(evF, sV);

    // main: K3 = split-fp16 GEMM on fp32 h1 -> fp16 Whh (no h1 precision loss)
    hgemm_split<<<dim3(NHID / HBN, NN / HBM), 256, 0, s0>>>(p_h1, Wa, p_Whh, NN, NHID, NHID);

    // join -> K5
    cudaStreamWaitEvent(s0, evF, 0);
    cudaStreamWaitEvent(s0, evSet, 0);
    k5_attention<<<NN, 256, 0, s0>>>(d_out);

    k6_gemm3<<<NN / 16, 256, 0, s0>>>(W3);
    k7_final<<<NN / 16, 256, 0, s0>>>(b3, d_out);
}